// round 1
// baseline (speedup 1.0000x reference)
#include <cuda_runtime.h>

typedef unsigned long long ull;

__device__ __forceinline__ ull pack2(float lo, float hi) {
    ull v; asm("mov.b64 %0, {%1, %2};" : "=l"(v) : "f"(lo), "f"(hi)); return v;
}
__device__ __forceinline__ void unpack2(ull v, float& lo, float& hi) {
    asm("mov.b64 {%0, %1}, %2;" : "=f"(lo), "=f"(hi) : "l"(v));
}
__device__ __forceinline__ void ffma2(ull& d, ull a, ull b) {
    asm("fma.rn.f32x2 %0, %1, %2, %0;" : "+l"(d) : "l"(a), "l"(b));
}

// Dice (inference BN, center=False scale=False): x * (alpha + (1-alpha)*sigmoid((x-m)*s))
__device__ __forceinline__ float dice_act(float x, float a, float c, float m, float s) {
    float nz = (m - x) * s;                 // -z
    float e  = __expf(nz);
    float p  = __fdividef(1.0f, 1.0f + e);  // sigmoid(z)
    return x * fmaf(c, p, a);
}

__global__ void __launch_bounds__(256) din_kernel(
    const float* __restrict__ query, const float* __restrict__ keys,
    const float* __restrict__ W0, const float* __restrict__ b0,
    const float* __restrict__ W1, const float* __restrict__ b1,
    const float* __restrict__ alpha0, const float* __restrict__ alpha1,
    const float* __restrict__ mm0, const float* __restrict__ mv0,
    const float* __restrict__ mm1, const float* __restrict__ mv1,
    const float* __restrict__ ak, const float* __restrict__ ab,
    float* __restrict__ out)
{
    // Packed layouts (all 16B aligned for ld.shared.v2.u64):
    //  Mf: per-op-pair rows: float offset = op*24 + i2*4 + pos
    //      pos0 = M[2op][2i2], pos1 = M[2op+1][2i2], pos2 = M[2op][2i2+1], pos3 = M[2op+1][2i2+1]
    //  W1f: natural row-major [80][40] (consecutive j pairs are already packed pairs)
    //  Bf : base[o] natural order (consecutive o pairs = packed pairs)
    __shared__ __align__(16) float Mf[960];
    __shared__ __align__(16) float W1f[3200];
    __shared__ __align__(16) float ksh[2400];
    __shared__ __align__(16) float Bf[80];
    __shared__ __align__(16) float b1f[40];
    __shared__ float qs[12];
    __shared__ float a0s[80], c0s[80], m0s[80], s0s[80];
    __shared__ float a1s[40], c1s[40], m1s[40], s1s[40];
    __shared__ float aks[40];
    __shared__ float sc[200];
    __shared__ float psum[96];

    const int tid = threadIdx.x;
    const int b   = blockIdx.x;
    const float EPS = 1e-9f;

    if (tid < 12) qs[tid] = query[b * 12 + tid];
    __syncthreads();  // qs needed for M precompute

    // --- cooperative per-CTA precompute ---
    // keys tile -> shared (coalesced float4)
    {
        const float4* gk = (const float4*)(keys + (size_t)b * 2400);
        float4* sk = (float4*)ksh;
        for (int i = tid; i < 600; i += 256) sk[i] = gk[i];
    }
    // W1 -> shared (natural layout IS the packed layout)
    {
        const float4* gw = (const float4*)W1;
        float4* sw = (float4*)W1f;
        for (int i = tid; i < 800; i += 256) sw[i] = gw[i];
    }
    // M_b: M[o][i] = W0[12+i][o] - W0[24+i][o] + q_i * W0[36+i][o]
    for (int idx = tid; idx < 960; idx += 256) {
        int pos = idx & 3;
        int blk = idx >> 2;
        int op  = blk / 6;
        int i2  = blk % 6;
        int o   = 2 * op + (pos & 1);
        int i   = 2 * i2 + (pos >> 1);
        float m = W0[(12 + i) * 80 + o] - W0[(24 + i) * 80 + o]
                + qs[i] * W0[(36 + i) * 80 + o];
        Mf[idx] = m;
    }
    // base_b[o] = b0[o] + sum_i q_i * (W0[i][o] + W0[24+i][o]); dice0 params
    if (tid < 80) {
        int o = tid;
        float s = b0[o];
        #pragma unroll
        for (int i = 0; i < 12; ++i)
            s += qs[i] * (W0[i * 80 + o] + W0[(24 + i) * 80 + o]);
        Bf[o] = s;
        float a = alpha0[o];
        a0s[o] = a; c0s[o] = 1.0f - a;
        m0s[o] = mm0[o];
        s0s[o] = rsqrtf(mv0[o] + EPS);
    }
    if (tid < 40) {
        int o = tid;
        b1f[o] = b1[o];
        float a = alpha1[o];
        a1s[o] = a; c1s[o] = 1.0f - a;
        m1s[o] = mm1[o];
        s1s[o] = rsqrtf(mv1[o] + EPS);
        aks[o] = ak[o];
    }
    __syncthreads();

    // --- main per-position compute (one thread = one t) ---
    if (tid < 200) {
        const int t = tid;
        // pack k[i] into (k,k) f32x2 operands
        ull k2[12];
        #pragma unroll
        for (int i = 0; i < 12; ++i) {
            float kv = ksh[t * 12 + i];
            k2[i] = pack2(kv, kv);
        }
        // h1 accumulators: 20 packed pairs, init with b1
        ull h1[20];
        const ull* b1p = (const ull*)b1f;
        #pragma unroll
        for (int jp = 0; jp < 20; ++jp) h1[jp] = b1p[jp];

        const ull* Bp = (const ull*)Bf;

        #pragma unroll 4
        for (int op = 0; op < 40; ++op) {
            // layer 0: acc(2 channels) = base + k @ M (12 packed FMA, 6 LDS.128)
            ull acc = Bp[op];
            const ulonglong2* mrow = ((const ulonglong2*)Mf) + op * 6;
            #pragma unroll
            for (int i2 = 0; i2 < 6; ++i2) {
                ulonglong2 mm = mrow[i2];
                ffma2(acc, k2[2 * i2],     mm.x);
                ffma2(acc, k2[2 * i2 + 1], mm.y);
            }
            // Dice on both channels
            float x0, x1;
            unpack2(acc, x0, x1);
            int ch = 2 * op;
            float d0 = dice_act(x0, a0s[ch],     c0s[ch],     m0s[ch],     s0s[ch]);
            float d1 = dice_act(x1, a0s[ch + 1], c0s[ch + 1], m0s[ch + 1], s0s[ch + 1]);
            ull D0 = pack2(d0, d0);
            ull D1 = pack2(d1, d1);
            // layer 1 accumulate: two W1 rows (40 packed FMA, 20 LDS.128)
            const ulonglong2* w0r = ((const ulonglong2*)W1f) + ch * 10;
            const ulonglong2* w1r = w0r + 10;
            #pragma unroll
            for (int j4 = 0; j4 < 10; ++j4) {
                ulonglong2 wa = w0r[j4];
                ffma2(h1[2 * j4],     D0, wa.x);
                ffma2(h1[2 * j4 + 1], D0, wa.y);
            }
            #pragma unroll
            for (int j4 = 0; j4 < 10; ++j4) {
                ulonglong2 wb = w1r[j4];
                ffma2(h1[2 * j4],     D1, wb.x);
                ffma2(h1[2 * j4 + 1], D1, wb.y);
            }
        }

        // epilogue: Dice on h1 then dot with atten_kernel
        float score = ab[0];
        #pragma unroll
        for (int jp = 0; jp < 20; ++jp) {
            float y0, y1;
            unpack2(h1[jp], y0, y1);
            int j = 2 * jp;
            float e0 = dice_act(y0, a1s[j],     c1s[j],     m1s[j],     s1s[j]);
            float e1 = dice_act(y1, a1s[j + 1], c1s[j + 1], m1s[j + 1], s1s[j + 1]);
            score = fmaf(e0, aks[j], score);
            score = fmaf(e1, aks[j + 1], score);
        }
        sc[t] = score;
    }
    __syncthreads();

    // --- reduction: out[b][e] = sum_t sc[t] * keys[b][t][e] (UNMASKED, per reference bug) ---
    if (tid < 96) {
        int e = tid % 12;
        int c = tid / 12;     // 8 chunks of 25 positions
        float acc = 0.0f;
        int t0 = c * 25;
        #pragma unroll 5
        for (int t2 = t0; t2 < t0 + 25; ++t2)
            acc = fmaf(sc[t2], ksh[t2 * 12 + e], acc);
        psum[tid] = acc;
    }
    __syncthreads();
    if (tid < 12) {
        float acc = 0.0f;
        #pragma unroll
        for (int c = 0; c < 8; ++c) acc += psum[c * 12 + tid];
        out[b * 12 + tid] = acc;
    }
}

extern "C" void kernel_launch(void* const* d_in, const int* in_sizes, int n_in,
                              void* d_out, int out_size) {
    const float* query  = (const float*)d_in[0];
    const float* keys   = (const float*)d_in[1];
    // d_in[2] = mask (bool) -- intentionally unused: reference overwrites the
    // masked scores and matmuls the UNMASKED scores (bug reproduced faithfully)
    const float* W0     = (const float*)d_in[3];
    const float* b0     = (const float*)d_in[4];
    const float* W1     = (const float*)d_in[5];
    const float* b1     = (const float*)d_in[6];
    const float* alpha0 = (const float*)d_in[7];
    const float* alpha1 = (const float*)d_in[8];
    const float* mm0    = (const float*)d_in[9];
    const float* mv0    = (const float*)d_in[10];
    const float* mm1    = (const float*)d_in[11];
    const float* mv1    = (const float*)d_in[12];
    const float* ak     = (const float*)d_in[13];
    const float* ab     = (const float*)d_in[14];
    float* out = (float*)d_out;

    int B = out_size / 12;  // [B, 1, 12]
    din_kernel<<<B, 256>>>(query, keys, W0, b0, W1, b1, alpha0, alpha1,
                           mm0, mv0, mm1, mv1, ak, ab, out);
}

// round 2
// speedup vs baseline: 1.0508x; 1.0508x over previous
#include <cuda_runtime.h>

typedef unsigned long long ull;

__device__ __forceinline__ ull pack2(float lo, float hi) {
    ull v; asm("mov.b64 %0, {%1, %2};" : "=l"(v) : "f"(lo), "f"(hi)); return v;
}
__device__ __forceinline__ void unpack2(ull v, float& lo, float& hi) {
    asm("mov.b64 {%0, %1}, %2;" : "=f"(lo), "=f"(hi) : "l"(v));
}
__device__ __forceinline__ void ffma2(ull& d, ull a, ull b) {
    asm("fma.rn.f32x2 %0, %1, %2, %0;" : "+l"(d) : "l"(a), "l"(b));
}

// Dice (inference BN, center=False scale=False): x * (alpha + (1-alpha)*sigmoid((x-m)*s))
__device__ __forceinline__ float dice_act(float x, float a, float c, float m, float s) {
    float nz = (m - x) * s;                 // -z
    float e  = __expf(nz);
    float p  = __fdividef(1.0f, 1.0f + e);  // sigmoid(z)
    return x * fmaf(c, p, a);
}

__global__ void __launch_bounds__(128) din_kernel(
    const float* __restrict__ query, const float* __restrict__ keys,
    const float* __restrict__ W0, const float* __restrict__ b0,
    const float* __restrict__ W1, const float* __restrict__ b1,
    const float* __restrict__ alpha0, const float* __restrict__ alpha1,
    const float* __restrict__ mm0, const float* __restrict__ mv0,
    const float* __restrict__ mm1, const float* __restrict__ mv1,
    const float* __restrict__ ak, const float* __restrict__ ab,
    float* __restrict__ out)
{
    // Shared layouts (all 16B aligned):
    //  Md : duplicated M, float offset = o*24 + i2*4 + pos,
    //       floats { M[o][2i2], M[o][2i2], M[o][2i2+1], M[o][2i2+1] }
    //       -> one LDS.128 yields two (m,m) f32x2 operands (packing across positions)
    //  W1f: natural row-major [80][40] (consecutive j pairs are packed channel pairs)
    //  Bfd: base duplicated: Bfd[2o]=Bfd[2o+1]=base[o] -> ull load = (base,base)
    __shared__ __align__(16) float Md[1920];
    __shared__ __align__(16) float W1f[3200];
    __shared__ __align__(16) float ksh[2400];
    __shared__ __align__(16) float Bfd[160];
    __shared__ __align__(16) float b1f[40];
    __shared__ float qs[12];
    __shared__ float a0s[80], c0s[80], m0s[80], s0s[80];
    __shared__ float a1s[40], c1s[40], m1s[40], s1s[40];
    __shared__ float aks[40];
    __shared__ float sc[200];
    __shared__ float psum[96];

    const int tid = threadIdx.x;
    const int b   = blockIdx.x;
    const float EPS = 1e-9f;

    if (tid < 12) qs[tid] = query[b * 12 + tid];
    __syncthreads();  // qs needed for M precompute

    // --- cooperative per-CTA precompute ---
    {
        const float4* gk = (const float4*)(keys + (size_t)b * 2400);
        float4* sk = (float4*)ksh;
        for (int i = tid; i < 600; i += 128) sk[i] = gk[i];
    }
    {
        const float4* gw = (const float4*)W1;
        float4* sw = (float4*)W1f;
        for (int i = tid; i < 800; i += 128) sw[i] = gw[i];
    }
    // Md (duplicated): M[o][i] = W0[12+i][o] - W0[24+i][o] + q_i * W0[36+i][o]
    for (int idx = tid; idx < 1920; idx += 128) {
        int pos = idx & 3;
        int blk = idx >> 2;
        int o   = blk / 6;
        int i2  = blk % 6;
        int i   = 2 * i2 + (pos >> 1);
        float m = W0[(12 + i) * 80 + o] - W0[(24 + i) * 80 + o]
                + qs[i] * W0[(36 + i) * 80 + o];
        Md[idx] = m;
    }
    // base_b[o] = b0[o] + sum_i q_i * (W0[i][o] + W0[24+i][o]); dice0 params
    if (tid < 80) {
        int o = tid;
        float s = b0[o];
        #pragma unroll
        for (int i = 0; i < 12; ++i)
            s += qs[i] * (W0[i * 80 + o] + W0[(24 + i) * 80 + o]);
        Bfd[2 * o] = s; Bfd[2 * o + 1] = s;
        float a = alpha0[o];
        a0s[o] = a; c0s[o] = 1.0f - a;
        m0s[o] = mm0[o];
        s0s[o] = rsqrtf(mv0[o] + EPS);
    }
    if (tid < 40) {
        int o = tid;
        b1f[o] = b1[o];
        float a = alpha1[o];
        a1s[o] = a; c1s[o] = 1.0f - a;
        m1s[o] = mm1[o];
        s1s[o] = rsqrtf(mv1[o] + EPS);
        aks[o] = ak[o];
    }
    __syncthreads();

    // --- main compute: thread handles positions tA=tid and tB=tid+100 ---
    if (tid < 100) {
        const int tA = tid, tB = tid + 100;
        // k packed ACROSS positions: k2[i] = (kA_i, kB_i)
        ull k2[12];
        #pragma unroll
        for (int i = 0; i < 12; ++i)
            k2[i] = pack2(ksh[tA * 12 + i], ksh[tB * 12 + i]);

        // h1 accumulators: channel-packed pairs per position
        ull h1A[20], h1B[20];
        const ull* b1p = (const ull*)b1f;
        #pragma unroll
        for (int jp = 0; jp < 20; ++jp) { h1A[jp] = b1p[jp]; h1B[jp] = b1p[jp]; }

        const ull* Bp = (const ull*)Bfd;

        #pragma unroll 2
        for (int op = 0; op < 40; ++op) {
            const int ch = 2 * op;
            // layer 0 for channels ch, ch+1, BOTH positions (packed across pos):
            // acc0 = (xA_ch, xB_ch), acc1 = (xA_ch1, xB_ch1)
            ull acc0 = Bp[ch];
            ull acc1 = Bp[ch + 1];
            const ulonglong2* m0r = ((const ulonglong2*)Md) + ch * 6;
            const ulonglong2* m1r = m0r + 6;
            #pragma unroll
            for (int i2 = 0; i2 < 6; ++i2) {
                ulonglong2 ma = m0r[i2];
                ffma2(acc0, k2[2 * i2],     ma.x);
                ffma2(acc0, k2[2 * i2 + 1], ma.y);
                ulonglong2 mb = m1r[i2];
                ffma2(acc1, k2[2 * i2],     mb.x);
                ffma2(acc1, k2[2 * i2 + 1], mb.y);
            }
            // Dice on 4 scalars
            float xA0, xB0, xA1, xB1;
            unpack2(acc0, xA0, xB0);
            unpack2(acc1, xA1, xB1);
            float a_0 = a0s[ch],   c_0 = c0s[ch],   mB0 = m0s[ch],   sS0 = s0s[ch];
            float a_1 = a0s[ch+1], c_1 = c0s[ch+1], mB1 = m0s[ch+1], sS1 = s0s[ch+1];
            float dA0 = dice_act(xA0, a_0, c_0, mB0, sS0);
            float dB0 = dice_act(xB0, a_0, c_0, mB0, sS0);
            float dA1 = dice_act(xA1, a_1, c_1, mB1, sS1);
            float dB1 = dice_act(xB1, a_1, c_1, mB1, sS1);
            ull DA0 = pack2(dA0, dA0), DB0 = pack2(dB0, dB0);
            ull DA1 = pack2(dA1, dA1), DB1 = pack2(dB1, dB1);
            // layer 1: same W1 rows serve both positions (LDS amortized 2x)
            const ulonglong2* w0r = ((const ulonglong2*)W1f) + ch * 10;
            const ulonglong2* w1r = w0r + 10;
            #pragma unroll
            for (int j4 = 0; j4 < 10; ++j4) {
                ulonglong2 wa = w0r[j4];
                ffma2(h1A[2 * j4],     DA0, wa.x);
                ffma2(h1A[2 * j4 + 1], DA0, wa.y);
                ffma2(h1B[2 * j4],     DB0, wa.x);
                ffma2(h1B[2 * j4 + 1], DB0, wa.y);
            }
            #pragma unroll
            for (int j4 = 0; j4 < 10; ++j4) {
                ulonglong2 wb = w1r[j4];
                ffma2(h1A[2 * j4],     DA1, wb.x);
                ffma2(h1A[2 * j4 + 1], DA1, wb.y);
                ffma2(h1B[2 * j4],     DB1, wb.x);
                ffma2(h1B[2 * j4 + 1], DB1, wb.y);
            }
        }

        // epilogue: Dice on h1 then dot with atten_kernel, both positions
        float scoreA = ab[0], scoreB = scoreA;
        #pragma unroll
        for (int jp = 0; jp < 20; ++jp) {
            int j = 2 * jp;
            float a_0 = a1s[j],   c_0 = c1s[j],   mB0 = m1s[j],   sS0 = s1s[j];
            float a_1 = a1s[j+1], c_1 = c1s[j+1], mB1 = m1s[j+1], sS1 = s1s[j+1];
            float k0 = aks[j], k1 = aks[j + 1];
            float yA0, yA1, yB0, yB1;
            unpack2(h1A[jp], yA0, yA1);
            unpack2(h1B[jp], yB0, yB1);
            scoreA = fmaf(dice_act(yA0, a_0, c_0, mB0, sS0), k0, scoreA);
            scoreA = fmaf(dice_act(yA1, a_1, c_1, mB1, sS1), k1, scoreA);
            scoreB = fmaf(dice_act(yB0, a_0, c_0, mB0, sS0), k0, scoreB);
            scoreB = fmaf(dice_act(yB1, a_1, c_1, mB1, sS1), k1, scoreB);
        }
        sc[tA] = scoreA;
        sc[tB] = scoreB;
    }
    __syncthreads();

    // --- reduction: out[b][e] = sum_t sc[t] * keys[b][t][e] (UNMASKED, per reference bug) ---
    if (tid < 96) {
        int e = tid % 12;
        int c = tid / 12;     // 8 chunks of 25 positions
        float acc = 0.0f;
        int t0 = c * 25;
        #pragma unroll 5
        for (int t2 = t0; t2 < t0 + 25; ++t2)
            acc = fmaf(sc[t2], ksh[t2 * 12 + e], acc);
        psum[tid] = acc;
    }
    __syncthreads();
    if (tid < 12) {
        float acc = 0.0f;
        #pragma unroll
        for (int c = 0; c < 8; ++c) acc += psum[c * 12 + tid];
        out[b * 12 + tid] = acc;
    }
}

extern "C" void kernel_launch(void* const* d_in, const int* in_sizes, int n_in,
                              void* d_out, int out_size) {
    const float* query  = (const float*)d_in[0];
    const float* keys   = (const float*)d_in[1];
    // d_in[2] = mask (bool) -- intentionally unused: reference overwrites the
    // masked scores and matmuls the UNMASKED scores (bug reproduced faithfully)
    const float* W0     = (const float*)d_in[3];
    const float* b0     = (const float*)d_in[4];
    const float* W1     = (const float*)d_in[5];
    const float* b1     = (const float*)d_in[6];
    const float* alpha0 = (const float*)d_in[7];
    const float* alpha1 = (const float*)d_in[8];
    const float* mm0    = (const float*)d_in[9];
    const float* mv0    = (const float*)d_in[10];
    const float* mm1    = (const float*)d_in[11];
    const float* mv1    = (const float*)d_in[12];
    const float* ak     = (const float*)d_in[13];
    const float* ab     = (const float*)d_in[14];
    float* out = (float*)d_out;

    int B = out_size / 12;  // [B, 1, 12]
    din_kernel<<<B, 128>>>(query, keys, W0, b0, W1, b1, alpha0, alpha1,
                           mm0, mv0, mm1, mv1, ak, ab, out);
}

// round 3
// speedup vs baseline: 1.2479x; 1.1876x over previous
#include <cuda_runtime.h>

typedef unsigned long long ull;

__device__ __forceinline__ ull pack2(float lo, float hi) {
    ull v; asm("mov.b64 %0, {%1, %2};" : "=l"(v) : "f"(lo), "f"(hi)); return v;
}
__device__ __forceinline__ void unpack2(ull v, float& lo, float& hi) {
    asm("mov.b64 {%0, %1}, %2;" : "=f"(lo), "=f"(hi) : "l"(v));
}
__device__ __forceinline__ void ffma2(ull& d, ull a, ull b) {
    asm("fma.rn.f32x2 %0, %1, %2, %0;" : "+l"(d) : "l"(a), "l"(b));
}
__device__ __forceinline__ float tanhx(float x) {
    float y; asm("tanh.approx.f32 %0, %1;" : "=f"(y) : "f"(x)); return y;
}

// Dice via tanh: sigmoid(z)=0.5+0.5*tanh(z/2)
//   dice(x) = x * fma(C2, tanh(fma(x, S2, MS2)), A2)
// with A2=a+0.5(1-a), C2=0.5(1-a), S2=0.5*rsqrt(mv+eps), MS2=-mm*S2
__device__ __forceinline__ float dice4(float x, float4 c) {
    float z  = fmaf(x, c.z, c.w);
    float th = tanhx(z);
    return x * fmaf(c.y, th, c.x);
}

__global__ void __launch_bounds__(128) din_kernel(
    const float* __restrict__ query, const float* __restrict__ keys,
    const float* __restrict__ W0, const float* __restrict__ b0,
    const float* __restrict__ W1, const float* __restrict__ b1,
    const float* __restrict__ alpha0, const float* __restrict__ alpha1,
    const float* __restrict__ mm0, const float* __restrict__ mv0,
    const float* __restrict__ mm1, const float* __restrict__ mv1,
    const float* __restrict__ ak, const float* __restrict__ ab,
    float* __restrict__ out)
{
    // Shared layouts (all 16B aligned):
    //  Md : duplicated M, float offset = o*24 + i2*4 + pos,
    //       floats { M[o][2i2], M[o][2i2], M[o][2i2+1], M[o][2i2+1] }
    //       -> one LDS.128 yields two (m,m) f32x2 operands (packing across positions)
    //  W1f: natural row-major [80][40] (consecutive j pairs are packed channel pairs)
    //  Bfd: base duplicated: Bfd[2o]=Bfd[2o+1]=base[o] -> ull load = (base,base)
    //  d0c/d1c: per-channel Dice constants {A2, C2, S2, MS2} (d1c has ak folded in)
    __shared__ __align__(16) float Md[1920];
    __shared__ __align__(16) float W1f[3200];
    __shared__ __align__(16) float ksh[2400];
    __shared__ __align__(16) float Bfd[160];
    __shared__ __align__(16) float b1f[40];
    __shared__ __align__(16) float4 d0c[80];
    __shared__ __align__(16) float4 d1c[40];
    __shared__ float qs[12];
    __shared__ float sc[200];
    __shared__ float psum[96];
    __shared__ float score0;

    const int tid = threadIdx.x;
    const int b   = blockIdx.x;
    const float EPS = 1e-9f;

    if (tid < 12) qs[tid] = query[b * 12 + tid];
    if (tid == 0) score0 = ab[0];
    __syncthreads();  // qs needed for M precompute

    // --- cooperative per-CTA precompute ---
    {
        const float4* gk = (const float4*)(keys + (size_t)b * 2400);
        float4* sk = (float4*)ksh;
        for (int i = tid; i < 600; i += 128) sk[i] = gk[i];
    }
    {
        const float4* gw = (const float4*)W1;
        float4* sw = (float4*)W1f;
        for (int i = tid; i < 800; i += 128) sw[i] = gw[i];
    }
    // Md (duplicated): M[o][i] = W0[12+i][o] - W0[24+i][o] + q_i * W0[36+i][o]
    for (int idx = tid; idx < 1920; idx += 128) {
        int pos = idx & 3;
        int blk = idx >> 2;
        int o   = blk / 6;
        int i2  = blk % 6;
        int i   = 2 * i2 + (pos >> 1);
        float m = W0[(12 + i) * 80 + o] - W0[(24 + i) * 80 + o]
                + qs[i] * W0[(36 + i) * 80 + o];
        Md[idx] = m;
    }
    // base_b[o] = b0[o] + sum_i q_i * (W0[i][o] + W0[24+i][o]); dice0 constants
    if (tid < 80) {
        int o = tid;
        float s = b0[o];
        #pragma unroll
        for (int i = 0; i < 12; ++i)
            s += qs[i] * (W0[i * 80 + o] + W0[(24 + i) * 80 + o]);
        Bfd[2 * o] = s; Bfd[2 * o + 1] = s;
        float a  = alpha0[o];
        float c2 = 0.5f * (1.0f - a);
        float s2 = 0.5f * rsqrtf(mv0[o] + EPS);
        d0c[o] = make_float4(a + c2, c2, s2, -mm0[o] * s2);
    }
    if (tid < 40) {
        int o = tid;
        b1f[o] = b1[o];
        float a  = alpha1[o];
        float kk = ak[o];
        float c2 = 0.5f * (1.0f - a);
        float s2 = 0.5f * rsqrtf(mv1[o] + EPS);
        // ak folded into the Dice affine: score += y * fma(C2k, th, A2k)
        d1c[o] = make_float4((a + c2) * kk, c2 * kk, s2, -mm1[o] * s2);
    }
    __syncthreads();

    // --- main compute: thread handles positions tA=tid and tB=tid+100 ---
    if (tid < 100) {
        const int tA = tid, tB = tid + 100;
        // k packed ACROSS positions: k2[i] = (kA_i, kB_i)
        ull k2[12];
        #pragma unroll
        for (int i = 0; i < 12; ++i)
            k2[i] = pack2(ksh[tA * 12 + i], ksh[tB * 12 + i]);

        // h1 accumulators: channel-packed pairs per position
        ull h1A[20], h1B[20];
        const ull* b1p = (const ull*)b1f;
        #pragma unroll
        for (int jp = 0; jp < 20; ++jp) { h1A[jp] = b1p[jp]; h1B[jp] = b1p[jp]; }

        const ull* Bp = (const ull*)Bfd;

        #pragma unroll 2
        for (int op = 0; op < 40; ++op) {
            const int ch = 2 * op;
            // layer 0 for channels ch, ch+1, BOTH positions (packed across pos)
            ull acc0 = Bp[ch];
            ull acc1 = Bp[ch + 1];
            const ulonglong2* m0r = ((const ulonglong2*)Md) + ch * 6;
            const ulonglong2* m1r = m0r + 6;
            #pragma unroll
            for (int i2 = 0; i2 < 6; ++i2) {
                ulonglong2 ma = m0r[i2];
                ffma2(acc0, k2[2 * i2],     ma.x);
                ffma2(acc0, k2[2 * i2 + 1], ma.y);
                ulonglong2 mb = m1r[i2];
                ffma2(acc1, k2[2 * i2],     mb.x);
                ffma2(acc1, k2[2 * i2 + 1], mb.y);
            }
            // Dice on 4 scalars (tanh path)
            float xA0, xB0, xA1, xB1;
            unpack2(acc0, xA0, xB0);
            unpack2(acc1, xA1, xB1);
            float4 c0 = d0c[ch];
            float4 c1 = d0c[ch + 1];
            float dA0 = dice4(xA0, c0);
            float dB0 = dice4(xB0, c0);
            float dA1 = dice4(xA1, c1);
            float dB1 = dice4(xB1, c1);
            ull DA0 = pack2(dA0, dA0), DB0 = pack2(dB0, dB0);
            ull DA1 = pack2(dA1, dA1), DB1 = pack2(dB1, dB1);
            // layer 1: same W1 rows serve both positions (LDS amortized 2x)
            const ulonglong2* w0r = ((const ulonglong2*)W1f) + ch * 10;
            const ulonglong2* w1r = w0r + 10;
            #pragma unroll
            for (int j4 = 0; j4 < 10; ++j4) {
                ulonglong2 wa = w0r[j4];
                ffma2(h1A[2 * j4],     DA0, wa.x);
                ffma2(h1A[2 * j4 + 1], DA0, wa.y);
                ffma2(h1B[2 * j4],     DB0, wa.x);
                ffma2(h1B[2 * j4 + 1], DB0, wa.y);
            }
            #pragma unroll
            for (int j4 = 0; j4 < 10; ++j4) {
                ulonglong2 wb = w1r[j4];
                ffma2(h1A[2 * j4],     DA1, wb.x);
                ffma2(h1A[2 * j4 + 1], DA1, wb.y);
                ffma2(h1B[2 * j4],     DB1, wb.x);
                ffma2(h1B[2 * j4 + 1], DB1, wb.y);
            }
        }

        // epilogue: Dice(+ak folded) on h1, accumulate scores
        float scoreA = score0, scoreB = score0;
        #pragma unroll
        for (int jp = 0; jp < 20; ++jp) {
            int j = 2 * jp;
            float4 c0 = d1c[j];
            float4 c1 = d1c[j + 1];
            float yA0, yA1, yB0, yB1;
            unpack2(h1A[jp], yA0, yA1);
            unpack2(h1B[jp], yB0, yB1);
            // score += y * fma(C2k, tanh(fma(y,S2,MS2)), A2k)
            scoreA = fmaf(yA0, fmaf(c0.y, tanhx(fmaf(yA0, c0.z, c0.w)), c0.x), scoreA);
            scoreA = fmaf(yA1, fmaf(c1.y, tanhx(fmaf(yA1, c1.z, c1.w)), c1.x), scoreA);
            scoreB = fmaf(yB0, fmaf(c0.y, tanhx(fmaf(yB0, c0.z, c0.w)), c0.x), scoreB);
            scoreB = fmaf(yB1, fmaf(c1.y, tanhx(fmaf(yB1, c1.z, c1.w)), c1.x), scoreB);
        }
        sc[tA] = scoreA;
        sc[tB] = scoreB;
    }
    __syncthreads();

    // --- reduction: out[b][e] = sum_t sc[t] * keys[b][t][e] (UNMASKED, per reference bug) ---
    if (tid < 96) {
        int e = tid % 12;
        int c = tid / 12;     // 8 chunks of 25 positions
        float acc = 0.0f;
        int t0 = c * 25;
        #pragma unroll 5
        for (int t2 = t0; t2 < t0 + 25; ++t2)
            acc = fmaf(sc[t2], ksh[t2 * 12 + e], acc);
        psum[tid] = acc;
    }
    __syncthreads();
    if (tid < 12) {
        float acc = 0.0f;
        #pragma unroll
        for (int c = 0; c < 8; ++c) acc += psum[c * 12 + tid];
        out[b * 12 + tid] = acc;
    }
}

extern "C" void kernel_launch(void* const* d_in, const int* in_sizes, int n_in,
                              void* d_out, int out_size) {
    const float* query  = (const float*)d_in[0];
    const float* keys   = (const float*)d_in[1];
    // d_in[2] = mask (bool) -- intentionally unused: reference overwrites the
    // masked scores and matmuls the UNMASKED scores (bug reproduced faithfully)
    const float* W0     = (const float*)d_in[3];
    const float* b0     = (const float*)d_in[4];
    const float* W1     = (const float*)d_in[5];
    const float* b1     = (const float*)d_in[6];
    const float* alpha0 = (const float*)d_in[7];
    const float* alpha1 = (const float*)d_in[8];
    const float* mm0    = (const float*)d_in[9];
    const float* mv0    = (const float*)d_in[10];
    const float* mm1    = (const float*)d_in[11];
    const float* mv1    = (const float*)d_in[12];
    const float* ak     = (const float*)d_in[13];
    const float* ab     = (const float*)d_in[14];
    float* out = (float*)d_out;

    int B = out_size / 12;  // [B, 1, 12]
    din_kernel<<<B, 128>>>(query, keys, W0, b0, W1, b1, alpha0, alpha1,
                           mm0, mv0, mm1, mv1, ak, ab, out);
}